// round 4
// baseline (speedup 1.0000x reference)
#include <cuda_runtime.h>
#include <math.h>

#define N_NODES 200000
#define N_EDGES 3200000
#define N_GRAPHS 1024

// ---------------- scratch (static device globals; no allocation) ----------------
__device__ int   g_is64;   // 1 if index inputs are int64, 0 if int32
__device__ int   g_src[N_EDGES];
__device__ int   g_dst[N_EDGES];
__device__ alignas(16) float g_norm[N_EDGES];
__device__ int   g_deg[N_NODES];
__device__ alignas(16) float g_dinv[N_NODES];
__device__ alignas(16) float g_buf0[(size_t)N_NODES * 64];
__device__ alignas(16) float g_buf1[(size_t)N_NODES * 64];
__device__ alignas(16) float g_buf2[(size_t)N_NODES * 64];
__device__ alignas(16) float g_gmax[N_GRAPHS * 32];
__device__ alignas(16) float g_gsum[N_GRAPHS * 32];
__device__ int   g_cnt[N_GRAPHS];

__device__ __forceinline__ float* dbuf(int s) {
    switch (s) {
        case 0:  return g_buf0;
        case 1:  return g_buf1;
        default: return g_buf2;
    }
}

// Vectorized global reduction (sm_90+): 4 floats per op, 16B aligned.
__device__ __forceinline__ void red_add_v4(float* addr, float4 v) {
    asm volatile("red.global.add.v4.f32 [%0], {%1, %2, %3, %4};"
                 :: "l"(addr), "f"(v.x), "f"(v.y), "f"(v.z), "f"(v.w)
                 : "memory");
}

// ---------------- kernels ----------------

// Probe: if edge_index is int64 (LE), the high 32-bit word of every value
// (< 200000) is 0, so odd int32 positions are all zero. Random int32 edge
// data can't match that for 64 consecutive odd slots.
__global__ void k_detect(const int* __restrict__ ei32) {
    if (threadIdx.x == 0 && blockIdx.x == 0) {
        int is64 = 1;
        #pragma unroll 1
        for (int i = 1; i < 128; i += 2)
            if (ei32[i] != 0) { is64 = 0; break; }
        g_is64 = is64;
    }
}

__global__ void k_init() {
    int i = blockIdx.x * blockDim.x + threadIdx.x;
    if (i < N_NODES) g_deg[i] = 0;
    if (i < N_GRAPHS * 32) { g_gmax[i] = 0.0f; g_gsum[i] = 0.0f; }
    if (i < N_GRAPHS) g_cnt[i] = 0;
}

__global__ void k_edges(const void* __restrict__ ei) {
    int e = blockIdx.x * blockDim.x + threadIdx.x;
    if (e >= N_EDGES) return;
    int s, d;
    if (g_is64) {
        const long long* p = (const long long*)ei;
        s = (int)p[e];
        d = (int)p[(size_t)N_EDGES + e];
    } else {
        const int* p = (const int*)ei;
        s = p[e];
        d = p[N_EDGES + e];
    }
    g_src[e] = s;
    g_dst[e] = d;
    atomicAdd(&g_deg[d], 1);
}

__global__ void k_dinv() {
    int i = blockIdx.x * blockDim.x + threadIdx.x;
    if (i >= N_NODES) return;
    g_dinv[i] = rsqrtf((float)g_deg[i] + 1.0f);  // +1 self-loop; always > 0
}

__global__ void k_norm() {
    int e = blockIdx.x * blockDim.x + threadIdx.x;
    if (e >= N_EDGES) return;
    g_norm[e] = g_dinv[g_src[e]] * g_dinv[g_dst[e]];
}

// tmp[N,FOUT] = hin[N,FIN] @ W[FIN,FOUT]
template <int FIN, int FOUT>
__global__ void k_matmul(const float* __restrict__ x_ext, int hinSel, int tmpSel,
                         const float* __restrict__ W) {
    constexpr int NPB = 256 / FOUT;  // nodes per block
    __shared__ float Ws[FIN * FOUT];
    __shared__ float Xs[NPB * FIN];

    const float* hin = (hinSel < 0) ? x_ext : dbuf(hinSel);
    float* tmp = dbuf(tmpSel);

    int tid = threadIdx.x;
    for (int k = tid; k < FIN * FOUT; k += 256) Ws[k] = W[k];

    int base = blockIdx.x * NPB;
    for (int k = tid; k < NPB * FIN; k += 256) {
        int node = base + k / FIN;
        Xs[k] = (node < N_NODES) ? hin[(size_t)node * FIN + (k % FIN)] : 0.0f;
    }
    __syncthreads();

    int ln = tid / FOUT;
    int o  = tid % FOUT;
    int node = base + ln;
    if (node >= N_NODES) return;

    float acc = 0.0f;
    #pragma unroll
    for (int i = 0; i < FIN; i++)
        acc = fmaf(Xs[ln * FIN + i], Ws[i * FOUT + o], acc);
    tmp[(size_t)node * FOUT + o] = acc;
}

// agg[i,:] = tmp[i,:] * dinv[i]^2   (self-loop contribution, also initializes agg)
template <int F>
__global__ void k_selfloop(int tmpSel, int aggSel) {
    constexpr int TOT = N_NODES * (F / 4);
    int idx = blockIdx.x * blockDim.x + threadIdx.x;
    if (idx >= TOT) return;
    const float* tmp = dbuf(tmpSel);
    float* agg = dbuf(aggSel);
    int node = idx / (F / 4);
    float di = g_dinv[node];
    float w = di * di;
    float4 v = ((const float4*)tmp)[idx];
    v.x *= w; v.y *= w; v.z *= w; v.w *= w;
    ((float4*)agg)[idx] = v;
}

// agg[dst,:] += tmp[src,:] * norm[e]   for all edges (F/4 threads per edge)
template <int F>
__global__ void k_scatter(int tmpSel, int aggSel) {
    constexpr int TPE = F / 4;
    int gt = blockIdx.x * blockDim.x + threadIdx.x;
    int e = gt / TPE;
    int j = gt % TPE;
    if (e >= N_EDGES) return;
    const float* tmp = dbuf(tmpSel);
    float* agg = dbuf(aggSel);
    int s = g_src[e];
    int d = g_dst[e];
    float nrm = g_norm[e];
    float4 v = *(const float4*)(tmp + (size_t)s * F + 4 * j);
    v.x *= nrm; v.y *= nrm; v.z *= nrm; v.w *= nrm;
    red_add_v4(agg + (size_t)d * F + 4 * j, v);
}

// in-place: agg = act(agg + b).  ACT: 0 = tanh, 1 = relu
template <int F, int ACT>
__global__ void k_act(int aggSel, const float* __restrict__ b) {
    constexpr int TOT = N_NODES * (F / 4);
    int idx = blockIdx.x * blockDim.x + threadIdx.x;
    if (idx >= TOT) return;
    float* agg = dbuf(aggSel);
    int fb = (idx % (F / 4)) * 4;
    float4 v = ((float4*)agg)[idx];
    v.x += b[fb + 0]; v.y += b[fb + 1]; v.z += b[fb + 2]; v.w += b[fb + 3];
    if (ACT == 0) {
        v.x = tanhf(v.x); v.y = tanhf(v.y); v.z = tanhf(v.z); v.w = tanhf(v.w);
    } else {
        v.x = fmaxf(v.x, 0.0f); v.y = fmaxf(v.y, 0.0f);
        v.z = fmaxf(v.z, 0.0f); v.w = fmaxf(v.w, 0.0f);
    }
    ((float4*)agg)[idx] = v;
}

// global max + sum pool over graphs. h is [N, 32], values >= 0 (post-ReLU),
// so float max == int-bitpattern max with 0-init.
__global__ void k_pool(int hSel, const void* __restrict__ batch) {
    int gt = blockIdx.x * blockDim.x + threadIdx.x;
    int i = gt / 8;
    int j = gt % 8;
    if (i >= N_NODES) return;
    const float* h = dbuf(hSel);
    int g;
    if (g_is64) g = (int)((const long long*)batch)[i];
    else        g = ((const int*)batch)[i];
    float4 v = *(const float4*)(h + (size_t)i * 32 + 4 * j);
    red_add_v4(&g_gsum[g * 32 + 4 * j], v);
    int* mx = (int*)&g_gmax[g * 32 + 4 * j];
    atomicMax(mx + 0, __float_as_int(v.x));
    atomicMax(mx + 1, __float_as_int(v.y));
    atomicMax(mx + 2, __float_as_int(v.z));
    atomicMax(mx + 3, __float_as_int(v.w));
    if (j == 0) atomicAdd(&g_cnt[g], 1);
}

// out[g, o] = concat(gmax, gmean) @ Wout + bout
__global__ void k_out(const float* __restrict__ Wout, const float* __restrict__ bout,
                      float* __restrict__ out) {
    int idx = blockIdx.x * blockDim.x + threadIdx.x;
    if (idx >= N_GRAPHS * 10) return;
    int g = idx / 10;
    int o = idx % 10;
    float cnt = (float)g_cnt[g];
    float inv = 1.0f / fmaxf(cnt, 1.0f);
    float acc = bout[o];
    #pragma unroll 8
    for (int f = 0; f < 32; f++) {
        acc = fmaf(g_gmax[g * 32 + f], Wout[f * 10 + o], acc);
        acc = fmaf(g_gsum[g * 32 + f] * inv, Wout[(32 + f) * 10 + o], acc);
    }
    out[idx] = acc;
}

// ---------------- launch ----------------

static inline int cdiv(long long a, int b) { return (int)((a + b - 1) / b); }

extern "C" void kernel_launch(void* const* d_in, const int* in_sizes, int n_in,
                              void* d_out, int out_size) {
    const float* x     = (const float*)d_in[0];
    const void*  ei    = d_in[1];
    const void*  batch = d_in[2];
    const float* W0   = (const float*)d_in[3];
    const float* b0   = (const float*)d_in[4];
    const float* W1   = (const float*)d_in[5];
    const float* b1   = (const float*)d_in[6];
    const float* W2   = (const float*)d_in[7];
    const float* b2   = (const float*)d_in[8];
    const float* W3   = (const float*)d_in[9];
    const float* b3   = (const float*)d_in[10];
    const float* Wout = (const float*)d_in[11];
    const float* bout = (const float*)d_in[12];
    float* out = (float*)d_out;

    const int T = 256;

    k_detect<<<1, 32>>>((const int*)ei);
    k_init<<<cdiv(N_NODES, T), T>>>();
    k_edges<<<cdiv(N_EDGES, T), T>>>(ei);
    k_dinv<<<cdiv(N_NODES, T), T>>>();
    k_norm<<<cdiv(N_EDGES, T), T>>>();

    // Layer 0: x[N,8] -> 64, tanh.  tmp=buf0, agg=buf1
    k_matmul<8, 64><<<cdiv(N_NODES, 256 / 64), T>>>(x, -1, 0, W0);
    k_selfloop<64><<<cdiv((long long)N_NODES * 16, T), T>>>(0, 1);
    k_scatter<64><<<cdiv((long long)N_EDGES * 16, T), T>>>(0, 1);
    k_act<64, 0><<<cdiv((long long)N_NODES * 16, T), T>>>(1, b0);

    // Layer 1: 64 -> 64, relu.  hin=buf1, tmp=buf0, agg=buf2
    k_matmul<64, 64><<<cdiv(N_NODES, 256 / 64), T>>>(nullptr, 1, 0, W1);
    k_selfloop<64><<<cdiv((long long)N_NODES * 16, T), T>>>(0, 2);
    k_scatter<64><<<cdiv((long long)N_EDGES * 16, T), T>>>(0, 2);
    k_act<64, 1><<<cdiv((long long)N_NODES * 16, T), T>>>(2, b1);

    // Layer 2: 64 -> 32, relu.  hin=buf2, tmp=buf0, agg=buf1
    k_matmul<64, 32><<<cdiv(N_NODES, 256 / 32), T>>>(nullptr, 2, 0, W2);
    k_selfloop<32><<<cdiv((long long)N_NODES * 8, T), T>>>(0, 1);
    k_scatter<32><<<cdiv((long long)N_EDGES * 8, T), T>>>(0, 1);
    k_act<32, 1><<<cdiv((long long)N_NODES * 8, T), T>>>(1, b2);

    // Layer 3: 32 -> 32, relu.  hin=buf1, tmp=buf0, agg=buf2
    k_matmul<32, 32><<<cdiv(N_NODES, 256 / 32), T>>>(nullptr, 1, 0, W3);
    k_selfloop<32><<<cdiv((long long)N_NODES * 8, T), T>>>(0, 2);
    k_scatter<32><<<cdiv((long long)N_EDGES * 8, T), T>>>(0, 2);
    k_act<32, 1><<<cdiv((long long)N_NODES * 8, T), T>>>(2, b3);

    // Pool h4 (buf2) and project
    k_pool<<<cdiv((long long)N_NODES * 8, T), T>>>(2, batch);
    k_out<<<cdiv(N_GRAPHS * 10, T), T>>>(Wout, bout, out);
}

// round 7
// speedup vs baseline: 1.3842x; 1.3842x over previous
#include <cuda_runtime.h>
#include <math.h>

#define N_NODES 200000
#define N_EDGES 3200000
#define N_GRAPHS 1024
#define NB 782   // cdiv(N_NODES, 256)

// ---------------- scratch (static device globals; no allocation) ----------------
__device__ int   g_is64;
__device__ int   g_src[N_EDGES];
__device__ int   g_dst[N_EDGES];
__device__ alignas(16) int2 g_packed[N_EDGES];   // CSR payload: {src, bitcast(norm)}
__device__ int   g_deg[N_NODES];
__device__ int   g_rowstart[N_NODES + 1];
__device__ int   g_cursor[N_NODES];
__device__ int   g_bsum[1024];
__device__ int   g_boff[1024];
__device__ alignas(16) float g_dinv[N_NODES];
__device__ alignas(16) float g_buf0[(size_t)N_NODES * 64];
__device__ alignas(16) float g_buf1[(size_t)N_NODES * 64];
__device__ alignas(16) float g_buf2[(size_t)N_NODES * 64];
__device__ alignas(16) float g_gmax[N_GRAPHS * 32];
__device__ alignas(16) float g_gsum[N_GRAPHS * 32];
__device__ int   g_cnt[N_GRAPHS];

__device__ __forceinline__ float* dbuf(int s) {
    switch (s) {
        case 0:  return g_buf0;
        case 1:  return g_buf1;
        default: return g_buf2;
    }
}

// ---------------- preprocessing ----------------

// dtype probe: int64 indices (<200000) have all-zero high words.
__global__ void k_detect(const int* __restrict__ ei32) {
    if (threadIdx.x == 0 && blockIdx.x == 0) {
        int is64 = 1;
        #pragma unroll 1
        for (int i = 1; i < 128; i += 2)
            if (ei32[i] != 0) { is64 = 0; break; }
        g_is64 = is64;
    }
}

__global__ void k_init() {
    int i = blockIdx.x * blockDim.x + threadIdx.x;
    if (i < N_NODES) g_deg[i] = 0;
    if (i < N_GRAPHS * 32) { g_gmax[i] = 0.0f; g_gsum[i] = 0.0f; }
    if (i < N_GRAPHS) g_cnt[i] = 0;
    if (i == 0) g_rowstart[N_NODES] = N_EDGES;
}

__global__ void k_edges(const void* __restrict__ ei) {
    int e = blockIdx.x * blockDim.x + threadIdx.x;
    if (e >= N_EDGES) return;
    int s, d;
    if (g_is64) {
        const long long* p = (const long long*)ei;
        s = (int)p[e];
        d = (int)p[(size_t)N_EDGES + e];
    } else {
        const int* p = (const int*)ei;
        s = p[e];
        d = p[N_EDGES + e];
    }
    g_src[e] = s;
    g_dst[e] = d;
    atomicAdd(&g_deg[d], 1);
}

__global__ void k_dinv() {
    int i = blockIdx.x * blockDim.x + threadIdx.x;
    if (i >= N_NODES) return;
    g_dinv[i] = rsqrtf((float)g_deg[i] + 1.0f);  // +1 self-loop; always > 0
}

// --- exclusive prefix sum of g_deg -> g_rowstart (3 kernels) ---
__global__ void k_scanA() {
    __shared__ int s[256];
    int i = blockIdx.x * 256 + threadIdx.x;
    s[threadIdx.x] = (i < N_NODES) ? g_deg[i] : 0;
    __syncthreads();
    for (int off = 128; off > 0; off >>= 1) {
        if (threadIdx.x < off) s[threadIdx.x] += s[threadIdx.x + off];
        __syncthreads();
    }
    if (threadIdx.x == 0) g_bsum[blockIdx.x] = s[0];
}

__global__ void k_scanB() {
    __shared__ int s[1024];
    int t = threadIdx.x;
    int own = (t < NB) ? g_bsum[t] : 0;
    s[t] = own;
    __syncthreads();
    for (int off = 1; off < 1024; off <<= 1) {
        int x = (t >= off) ? s[t - off] : 0;
        __syncthreads();
        s[t] += x;
        __syncthreads();
    }
    if (t < NB) g_boff[t] = s[t] - own;  // exclusive
}

__global__ void k_scanC() {
    __shared__ int s[256];
    int i = blockIdx.x * 256 + threadIdx.x;
    int v = (i < N_NODES) ? g_deg[i] : 0;
    s[threadIdx.x] = v;
    __syncthreads();
    for (int off = 1; off < 256; off <<= 1) {
        int x = (threadIdx.x >= off) ? s[threadIdx.x - off] : 0;
        __syncthreads();
        s[threadIdx.x] += x;
        __syncthreads();
    }
    if (i < N_NODES) {
        int start = g_boff[blockIdx.x] + s[threadIdx.x] - v;  // exclusive
        g_rowstart[i] = start;
        g_cursor[i] = start;
    }
}

__global__ void k_fill() {
    int e = blockIdx.x * blockDim.x + threadIdx.x;
    if (e >= N_EDGES) return;
    int s = g_src[e];
    int d = g_dst[e];
    float nrm = g_dinv[s] * g_dinv[d];
    int pos = atomicAdd(&g_cursor[d], 1);
    g_packed[pos] = make_int2(s, __float_as_int(nrm));
}

// ---------------- dense layers ----------------

// tmp[N,FOUT] = hin[N,FIN] @ W[FIN,FOUT]
template <int FIN, int FOUT>
__global__ void k_matmul(const float* __restrict__ x_ext, int hinSel, int tmpSel,
                         const float* __restrict__ W) {
    constexpr int NPB = 256 / FOUT;  // nodes per block
    __shared__ float Ws[FIN * FOUT];
    __shared__ float Xs[NPB * FIN];

    const float* hin = (hinSel < 0) ? x_ext : dbuf(hinSel);
    float* tmp = dbuf(tmpSel);

    int tid = threadIdx.x;
    for (int k = tid; k < FIN * FOUT; k += 256) Ws[k] = W[k];

    int base = blockIdx.x * NPB;
    for (int k = tid; k < NPB * FIN; k += 256) {
        int node = base + k / FIN;
        Xs[k] = (node < N_NODES) ? hin[(size_t)node * FIN + (k % FIN)] : 0.0f;
    }
    __syncthreads();

    int ln = tid / FOUT;
    int o  = tid % FOUT;
    int node = base + ln;
    if (node >= N_NODES) return;

    float acc = 0.0f;
    #pragma unroll
    for (int i = 0; i < FIN; i++)
        acc = fmaf(Xs[ln * FIN + i], Ws[i * FOUT + o], acc);
    tmp[(size_t)node * FOUT + o] = acc;
}

// ---------------- fused aggregate (CSR gather, no atomics) ----------------
// One warp per node: out[i] = act( selfloop + sum_{e in CSR[i]} tmp[src_e]*norm_e + b )
// ACT: 0 = tanh, 1 = relu.  POOL=1 (F=32 only): pool directly, no out write.
template <int F, int ACT, int POOL>
__global__ void k_agg(int tmpSel, int outSel, const float* __restrict__ b,
                      const void* __restrict__ batch) {
    const float* __restrict__ tmp = dbuf(tmpSel);
    int gw = (blockIdx.x * blockDim.x + threadIdx.x) >> 5;
    int lane = threadIdx.x & 31;
    if (gw >= N_NODES) return;
    const int i = gw;

    float di = g_dinv[i];
    float selfw = di * di;
    float acc0, acc1 = 0.0f;
    if (F == 64) {
        float2 v = *(const float2*)(tmp + (size_t)i * 64 + lane * 2);
        acc0 = v.x * selfw; acc1 = v.y * selfw;
    } else {
        acc0 = tmp[(size_t)i * 32 + lane] * selfw;
    }

    int s0 = g_rowstart[i];
    int s1 = g_rowstart[i + 1];
    #pragma unroll 2
    for (int k = s0; k < s1; k++) {
        int2 p = g_packed[k];
        float nrm = __int_as_float(p.y);
        const float* row = tmp + (size_t)p.x * F;
        if (F == 64) {
            float2 v = *(const float2*)(row + lane * 2);
            acc0 = fmaf(v.x, nrm, acc0);
            acc1 = fmaf(v.y, nrm, acc1);
        } else {
            acc0 = fmaf(row[lane], nrm, acc0);
        }
    }

    if (F == 64) { acc0 += b[lane * 2]; acc1 += b[lane * 2 + 1]; }
    else         { acc0 += b[lane]; }

    if (ACT == 0) { acc0 = tanhf(acc0); if (F == 64) acc1 = tanhf(acc1); }
    else          { acc0 = fmaxf(acc0, 0.0f); if (F == 64) acc1 = fmaxf(acc1, 0.0f); }

    if (POOL) {
        int g;
        if (g_is64) g = (int)((const long long*)batch)[i];
        else        g = ((const int*)batch)[i];
        atomicAdd(&g_gsum[g * 32 + lane], acc0);
        atomicMax((int*)&g_gmax[g * 32 + lane], __float_as_int(acc0));  // acc0 >= 0
        if (lane == 0) atomicAdd(&g_cnt[g], 1);
    } else {
        float* out = dbuf(outSel);
        if (F == 64) {
            *(float2*)(out + (size_t)i * 64 + lane * 2) = make_float2(acc0, acc1);
        } else {
            out[(size_t)i * 32 + lane] = acc0;
        }
    }
}

// out[g, o] = concat(gmax, gmean) @ Wout + bout
__global__ void k_out(const float* __restrict__ Wout, const float* __restrict__ bout,
                      float* __restrict__ out) {
    int idx = blockIdx.x * blockDim.x + threadIdx.x;
    if (idx >= N_GRAPHS * 10) return;
    int g = idx / 10;
    int o = idx % 10;
    float cnt = (float)g_cnt[g];
    float inv = 1.0f / fmaxf(cnt, 1.0f);
    float acc = bout[o];
    #pragma unroll 8
    for (int f = 0; f < 32; f++) {
        acc = fmaf(g_gmax[g * 32 + f], Wout[f * 10 + o], acc);
        acc = fmaf(g_gsum[g * 32 + f] * inv, Wout[(32 + f) * 10 + o], acc);
    }
    out[idx] = acc;
}

// ---------------- launch ----------------

static inline int cdiv(long long a, int b) { return (int)((a + b - 1) / b); }

extern "C" void kernel_launch(void* const* d_in, const int* in_sizes, int n_in,
                              void* d_out, int out_size) {
    const float* x     = (const float*)d_in[0];
    const void*  ei    = d_in[1];
    const void*  batch = d_in[2];
    const float* W0   = (const float*)d_in[3];
    const float* b0   = (const float*)d_in[4];
    const float* W1   = (const float*)d_in[5];
    const float* b1   = (const float*)d_in[6];
    const float* W2   = (const float*)d_in[7];
    const float* b2   = (const float*)d_in[8];
    const float* W3   = (const float*)d_in[9];
    const float* b3   = (const float*)d_in[10];
    const float* Wout = (const float*)d_in[11];
    const float* bout = (const float*)d_in[12];
    float* out = (float*)d_out;

    const int T = 256;
    const int AGG_BLOCKS = cdiv((long long)N_NODES * 32, T);

    // preprocessing: probe, degrees, dinv, CSR
    k_detect<<<1, 32>>>((const int*)ei);
    k_init<<<cdiv(N_NODES, T), T>>>();
    k_edges<<<cdiv(N_EDGES, T), T>>>(ei);
    k_dinv<<<cdiv(N_NODES, T), T>>>();
    k_scanA<<<NB, 256>>>();
    k_scanB<<<1, 1024>>>();
    k_scanC<<<NB, 256>>>();
    k_fill<<<cdiv(N_EDGES, T), T>>>();

    // Layer 0: x[N,8] @ W0 -> tmp(buf0); agg+tanh -> h1(buf1)
    k_matmul<8, 64><<<cdiv(N_NODES, 256 / 64), T>>>(x, -1, 0, W0);
    k_agg<64, 0, 0><<<AGG_BLOCKS, T>>>(0, 1, b0, nullptr);

    // Layer 1: h1(buf1) @ W1 -> tmp(buf0); agg+relu -> h2(buf2)
    k_matmul<64, 64><<<cdiv(N_NODES, 256 / 64), T>>>(nullptr, 1, 0, W1);
    k_agg<64, 1, 0><<<AGG_BLOCKS, T>>>(0, 2, b1, nullptr);

    // Layer 2: h2(buf2) @ W2 -> tmp(buf0); agg+relu -> h3(buf1)
    k_matmul<64, 32><<<cdiv(N_NODES, 256 / 32), T>>>(nullptr, 2, 0, W2);
    k_agg<32, 1, 0><<<AGG_BLOCKS, T>>>(0, 1, b2, nullptr);

    // Layer 3: h3(buf1) @ W3 -> tmp(buf0); agg+relu fused with pooling
    k_matmul<32, 32><<<cdiv(N_NODES, 256 / 32), T>>>(nullptr, 1, 0, W3);
    k_agg<32, 1, 1><<<AGG_BLOCKS, T>>>(0, 2, b3, batch);

    k_out<<<cdiv(N_GRAPHS * 10, T), T>>>(Wout, bout, out);
}

// round 8
// speedup vs baseline: 1.5368x; 1.1102x over previous
#include <cuda_runtime.h>
#include <math.h>

#define N_NODES 200000
#define N_EDGES 3200000
#define N_GRAPHS 1024
#define NB 782   // cdiv(N_NODES, 256)

// ---------------- scratch (static device globals; no allocation) ----------------
__device__ int   g_is64;
__device__ int   g_src[N_EDGES];
__device__ int   g_dst[N_EDGES];
__device__ alignas(16) int2 g_packed[N_EDGES];   // CSR payload: {src, bitcast(norm)}
__device__ int   g_deg[N_NODES];
__device__ int   g_rowstart[N_NODES + 1];
__device__ int   g_cursor[N_NODES];
__device__ int   g_bsum[1024];
__device__ int   g_boff[1024];
__device__ alignas(16) float g_dinv[N_NODES];
__device__ alignas(16) float g_buf0[(size_t)N_NODES * 64];
__device__ alignas(16) float g_buf1[(size_t)N_NODES * 64];
__device__ alignas(16) float g_buf2[(size_t)N_NODES * 64];
__device__ alignas(16) float g_gmax[N_GRAPHS * 32];
__device__ alignas(16) float g_gsum[N_GRAPHS * 32];
__device__ int   g_cnt[N_GRAPHS];

__device__ __forceinline__ float* dbuf(int s) {
    switch (s) {
        case 0:  return g_buf0;
        case 1:  return g_buf1;
        default: return g_buf2;
    }
}

// ---------------- preprocessing ----------------

// dtype probe: int64 indices (<200000) have all-zero high words.
__global__ void k_detect(const int* __restrict__ ei32) {
    if (threadIdx.x == 0 && blockIdx.x == 0) {
        int is64 = 1;
        #pragma unroll 1
        for (int i = 1; i < 128; i += 2)
            if (ei32[i] != 0) { is64 = 0; break; }
        g_is64 = is64;
    }
}

__global__ void k_init() {
    int i = blockIdx.x * blockDim.x + threadIdx.x;
    if (i < N_NODES) g_deg[i] = 0;
    if (i < N_GRAPHS * 32) { g_gmax[i] = 0.0f; g_gsum[i] = 0.0f; }
    if (i < N_GRAPHS) g_cnt[i] = 0;
    if (i == 0) g_rowstart[N_NODES] = N_EDGES;
}

__global__ void k_edges(const void* __restrict__ ei) {
    int e = blockIdx.x * blockDim.x + threadIdx.x;
    if (e >= N_EDGES) return;
    int s, d;
    if (g_is64) {
        const long long* p = (const long long*)ei;
        s = (int)p[e];
        d = (int)p[(size_t)N_EDGES + e];
    } else {
        const int* p = (const int*)ei;
        s = p[e];
        d = p[N_EDGES + e];
    }
    g_src[e] = s;
    g_dst[e] = d;
    atomicAdd(&g_deg[d], 1);
}

__global__ void k_dinv() {
    int i = blockIdx.x * blockDim.x + threadIdx.x;
    if (i >= N_NODES) return;
    g_dinv[i] = rsqrtf((float)g_deg[i] + 1.0f);  // +1 self-loop; always > 0
}

// --- exclusive prefix sum of g_deg -> g_rowstart (3 kernels) ---
__global__ void k_scanA() {
    __shared__ int s[256];
    int i = blockIdx.x * 256 + threadIdx.x;
    s[threadIdx.x] = (i < N_NODES) ? g_deg[i] : 0;
    __syncthreads();
    for (int off = 128; off > 0; off >>= 1) {
        if (threadIdx.x < off) s[threadIdx.x] += s[threadIdx.x + off];
        __syncthreads();
    }
    if (threadIdx.x == 0) g_bsum[blockIdx.x] = s[0];
}

__global__ void k_scanB() {
    __shared__ int s[1024];
    int t = threadIdx.x;
    int own = (t < NB) ? g_bsum[t] : 0;
    s[t] = own;
    __syncthreads();
    for (int off = 1; off < 1024; off <<= 1) {
        int x = (t >= off) ? s[t - off] : 0;
        __syncthreads();
        s[t] += x;
        __syncthreads();
    }
    if (t < NB) g_boff[t] = s[t] - own;  // exclusive
}

__global__ void k_scanC() {
    __shared__ int s[256];
    int i = blockIdx.x * 256 + threadIdx.x;
    int v = (i < N_NODES) ? g_deg[i] : 0;
    s[threadIdx.x] = v;
    __syncthreads();
    for (int off = 1; off < 256; off <<= 1) {
        int x = (threadIdx.x >= off) ? s[threadIdx.x - off] : 0;
        __syncthreads();
        s[threadIdx.x] += x;
        __syncthreads();
    }
    if (i < N_NODES) {
        int start = g_boff[blockIdx.x] + s[threadIdx.x] - v;  // exclusive
        g_rowstart[i] = start;
        g_cursor[i] = start;
    }
}

__global__ void k_fill() {
    int e = blockIdx.x * blockDim.x + threadIdx.x;
    if (e >= N_EDGES) return;
    int s = g_src[e];
    int d = g_dst[e];
    float nrm = g_dinv[s] * g_dinv[d];
    int pos = atomicAdd(&g_cursor[d], 1);
    g_packed[pos] = make_int2(s, __float_as_int(nrm));
}

// ---------------- dense layers ----------------

// tmp[N,FOUT] = act(hin[N,FIN] @ W[FIN,FOUT] + b)   ACT: -1 none, 0 tanh, 1 relu
template <int FIN, int FOUT, int ACT>
__global__ void k_matmul(const float* __restrict__ x_ext, int hinSel, int tmpSel,
                         const float* __restrict__ W, const float* __restrict__ b) {
    constexpr int NPB = 256 / FOUT;  // nodes per block
    __shared__ float Ws[FIN * FOUT];
    __shared__ float Xs[NPB * FIN];

    const float* hin = (hinSel < 0) ? x_ext : dbuf(hinSel);
    float* tmp = dbuf(tmpSel);

    int tid = threadIdx.x;
    for (int k = tid; k < FIN * FOUT; k += 256) Ws[k] = W[k];

    int base = blockIdx.x * NPB;
    for (int k = tid; k < NPB * FIN; k += 256) {
        int node = base + k / FIN;
        Xs[k] = (node < N_NODES) ? hin[(size_t)node * FIN + (k % FIN)] : 0.0f;
    }
    __syncthreads();

    int ln = tid / FOUT;
    int o  = tid % FOUT;
    int node = base + ln;
    if (node >= N_NODES) return;

    float acc = (ACT >= 0) ? b[o] : 0.0f;
    #pragma unroll
    for (int i = 0; i < FIN; i++)
        acc = fmaf(Xs[ln * FIN + i], Ws[i * FOUT + o], acc);
    if (ACT == 0) acc = tanhf(acc);
    if (ACT == 1) acc = fmaxf(acc, 0.0f);
    tmp[(size_t)node * FOUT + o] = acc;
}

// ---------------- fused aggregates (CSR gather, no atomics) ----------------

// 8-wide aggregate of the RAW INPUT x: 8 lanes per node (4 nodes per warp).
// aggx[i] = selfw*x[i] + sum_e x[src_e]*norm_e   (no bias/act — folded into matmul)
__global__ void k_agg8(const float* __restrict__ x, int outSel) {
    int gt = blockIdx.x * blockDim.x + threadIdx.x;
    int i = gt >> 3;
    int f = gt & 7;
    if (i >= N_NODES) return;
    float* out = dbuf(outSel);

    float di = g_dinv[i];
    float a0 = x[(size_t)i * 8 + f] * di * di;
    float a1 = 0.0f, a2 = 0.0f, a3 = 0.0f;

    int k = g_rowstart[i];
    int s1 = g_rowstart[i + 1];
    for (; k + 4 <= s1; k += 4) {
        int2 p0 = g_packed[k + 0];
        int2 p1 = g_packed[k + 1];
        int2 p2 = g_packed[k + 2];
        int2 p3 = g_packed[k + 3];
        a0 = fmaf(x[(size_t)p0.x * 8 + f], __int_as_float(p0.y), a0);
        a1 = fmaf(x[(size_t)p1.x * 8 + f], __int_as_float(p1.y), a1);
        a2 = fmaf(x[(size_t)p2.x * 8 + f], __int_as_float(p2.y), a2);
        a3 = fmaf(x[(size_t)p3.x * 8 + f], __int_as_float(p3.y), a3);
    }
    for (; k < s1; k++) {
        int2 p = g_packed[k];
        a0 = fmaf(x[(size_t)p.x * 8 + f], __int_as_float(p.y), a0);
    }
    out[(size_t)i * 8 + f] = a0 + a1 + a2 + a3;
}

// One warp per node: out[i] = act( selfloop + sum_e tmp[src_e]*norm_e + b )
// ACT: 0 = tanh, 1 = relu.  POOL=1 (F=32 only): pool directly, no out write.
template <int F, int ACT, int POOL>
__global__ void k_agg(int tmpSel, int outSel, const float* __restrict__ b,
                      const void* __restrict__ batch) {
    const float* __restrict__ tmp = dbuf(tmpSel);
    int gw = (blockIdx.x * blockDim.x + threadIdx.x) >> 5;
    int lane = threadIdx.x & 31;
    if (gw >= N_NODES) return;
    const int i = gw;

    float di = g_dinv[i];
    float selfw = di * di;

    float a0x = 0.f, a0y = 0.f, a1x = 0.f, a1y = 0.f;
    float a2x = 0.f, a2y = 0.f, a3x = 0.f, a3y = 0.f;

    if (F == 64) {
        float2 v = *(const float2*)(tmp + (size_t)i * 64 + lane * 2);
        a0x = v.x * selfw; a0y = v.y * selfw;
    } else {
        a0x = tmp[(size_t)i * 32 + lane] * selfw;
    }

    int k = g_rowstart[i];
    int s1 = g_rowstart[i + 1];
    for (; k + 4 <= s1; k += 4) {
        int2 p0 = g_packed[k + 0];
        int2 p1 = g_packed[k + 1];
        int2 p2 = g_packed[k + 2];
        int2 p3 = g_packed[k + 3];
        if (F == 64) {
            float2 v0 = *(const float2*)(tmp + (size_t)p0.x * 64 + lane * 2);
            float2 v1 = *(const float2*)(tmp + (size_t)p1.x * 64 + lane * 2);
            float2 v2 = *(const float2*)(tmp + (size_t)p2.x * 64 + lane * 2);
            float2 v3 = *(const float2*)(tmp + (size_t)p3.x * 64 + lane * 2);
            float n0 = __int_as_float(p0.y), n1 = __int_as_float(p1.y);
            float n2 = __int_as_float(p2.y), n3 = __int_as_float(p3.y);
            a0x = fmaf(v0.x, n0, a0x); a0y = fmaf(v0.y, n0, a0y);
            a1x = fmaf(v1.x, n1, a1x); a1y = fmaf(v1.y, n1, a1y);
            a2x = fmaf(v2.x, n2, a2x); a2y = fmaf(v2.y, n2, a2y);
            a3x = fmaf(v3.x, n3, a3x); a3y = fmaf(v3.y, n3, a3y);
        } else {
            float v0 = tmp[(size_t)p0.x * 32 + lane];
            float v1 = tmp[(size_t)p1.x * 32 + lane];
            float v2 = tmp[(size_t)p2.x * 32 + lane];
            float v3 = tmp[(size_t)p3.x * 32 + lane];
            a0x = fmaf(v0, __int_as_float(p0.y), a0x);
            a1x = fmaf(v1, __int_as_float(p1.y), a1x);
            a2x = fmaf(v2, __int_as_float(p2.y), a2x);
            a3x = fmaf(v3, __int_as_float(p3.y), a3x);
        }
    }
    for (; k < s1; k++) {
        int2 p = g_packed[k];
        float nrm = __int_as_float(p.y);
        if (F == 64) {
            float2 v = *(const float2*)(tmp + (size_t)p.x * 64 + lane * 2);
            a0x = fmaf(v.x, nrm, a0x); a0y = fmaf(v.y, nrm, a0y);
        } else {
            a0x = fmaf(tmp[(size_t)p.x * 32 + lane], nrm, a0x);
        }
    }

    float acc0 = (a0x + a1x) + (a2x + a3x);
    float acc1 = (a0y + a1y) + (a2y + a3y);

    if (F == 64) { acc0 += b[lane * 2]; acc1 += b[lane * 2 + 1]; }
    else         { acc0 += b[lane]; }

    if (ACT == 0) { acc0 = tanhf(acc0); if (F == 64) acc1 = tanhf(acc1); }
    else          { acc0 = fmaxf(acc0, 0.0f); if (F == 64) acc1 = fmaxf(acc1, 0.0f); }

    if (POOL) {
        int g;
        if (g_is64) g = (int)((const long long*)batch)[i];
        else        g = ((const int*)batch)[i];
        atomicAdd(&g_gsum[g * 32 + lane], acc0);
        atomicMax((int*)&g_gmax[g * 32 + lane], __float_as_int(acc0));  // acc0 >= 0
        if (lane == 0) atomicAdd(&g_cnt[g], 1);
    } else {
        float* out = dbuf(outSel);
        if (F == 64) {
            *(float2*)(out + (size_t)i * 64 + lane * 2) = make_float2(acc0, acc1);
        } else {
            out[(size_t)i * 32 + lane] = acc0;
        }
    }
}

// out[g, o] = concat(gmax, gmean) @ Wout + bout
__global__ void k_out(const float* __restrict__ Wout, const float* __restrict__ bout,
                      float* __restrict__ out) {
    int idx = blockIdx.x * blockDim.x + threadIdx.x;
    if (idx >= N_GRAPHS * 10) return;
    int g = idx / 10;
    int o = idx % 10;
    float cnt = (float)g_cnt[g];
    float inv = 1.0f / fmaxf(cnt, 1.0f);
    float acc = bout[o];
    #pragma unroll 8
    for (int f = 0; f < 32; f++) {
        acc = fmaf(g_gmax[g * 32 + f], Wout[f * 10 + o], acc);
        acc = fmaf(g_gsum[g * 32 + f] * inv, Wout[(32 + f) * 10 + o], acc);
    }
    out[idx] = acc;
}

// ---------------- launch ----------------

static inline int cdiv(long long a, int b) { return (int)((a + b - 1) / b); }

extern "C" void kernel_launch(void* const* d_in, const int* in_sizes, int n_in,
                              void* d_out, int out_size) {
    const float* x     = (const float*)d_in[0];
    const void*  ei    = d_in[1];
    const void*  batch = d_in[2];
    const float* W0   = (const float*)d_in[3];
    const float* b0   = (const float*)d_in[4];
    const float* W1   = (const float*)d_in[5];
    const float* b1   = (const float*)d_in[6];
    const float* W2   = (const float*)d_in[7];
    const float* b2   = (const float*)d_in[8];
    const float* W3   = (const float*)d_in[9];
    const float* b3   = (const float*)d_in[10];
    const float* Wout = (const float*)d_in[11];
    const float* bout = (const float*)d_in[12];
    float* out = (float*)d_out;

    const int T = 256;
    const int AGG_BLOCKS = cdiv((long long)N_NODES * 32, T);

    // preprocessing: probe, degrees, dinv, CSR
    k_detect<<<1, 32>>>((const int*)ei);
    k_init<<<cdiv(N_NODES, T), T>>>();
    k_edges<<<cdiv(N_EDGES, T), T>>>(ei);
    k_dinv<<<cdiv(N_NODES, T), T>>>();
    k_scanA<<<NB, 256>>>();
    k_scanB<<<1, 1024>>>();
    k_scanC<<<NB, 256>>>();
    k_fill<<<cdiv(N_EDGES, T), T>>>();

    // Layer 0 (reordered via linearity): aggx = agg(x) [8-wide], then
    // h1 = tanh(aggx @ W0 + b0) fused in matmul epilogue.
    k_agg8<<<cdiv((long long)N_NODES * 8, T), T>>>(x, 2);             // aggx -> buf2
    k_matmul<8, 64, 0><<<cdiv(N_NODES, 256 / 64), T>>>(nullptr, 2, 1, W0, b0);  // h1 -> buf1

    // Layer 1: h1 @ W1 -> tmp(buf0); agg+bias+relu -> h2(buf2)
    k_matmul<64, 64, -1><<<cdiv(N_NODES, 256 / 64), T>>>(nullptr, 1, 0, W1, nullptr);
    k_agg<64, 1, 0><<<AGG_BLOCKS, T>>>(0, 2, b1, nullptr);

    // Layer 2: h2 @ W2 -> tmp(buf0); agg+bias+relu -> h3(buf1)
    k_matmul<64, 32, -1><<<cdiv(N_NODES, 256 / 32), T>>>(nullptr, 2, 0, W2, nullptr);
    k_agg<32, 1, 0><<<AGG_BLOCKS, T>>>(0, 1, b2, nullptr);

    // Layer 3: h3 @ W3 -> tmp(buf0); agg+bias+relu fused with pooling
    k_matmul<32, 32, -1><<<cdiv(N_NODES, 256 / 32), T>>>(nullptr, 1, 0, W3, nullptr);
    k_agg<32, 1, 1><<<AGG_BLOCKS, T>>>(0, 2, b3, batch);

    k_out<<<cdiv(N_GRAPHS * 10, T), T>>>(Wout, bout, out);
}

// round 9
// speedup vs baseline: 1.6788x; 1.0924x over previous
#include <cuda_runtime.h>
#include <cuda_fp16.h>
#include <math.h>

#define N_NODES 200000
#define N_EDGES 3200000
#define N_GRAPHS 1024
#define NB 782   // cdiv(N_NODES, 256)

// ---------------- scratch (static device globals; no allocation) ----------------
__device__ int   g_is64;
__device__ alignas(16) int2 g_packed[N_EDGES];   // CSR payload: {src, bitcast(norm)}
__device__ int   g_deg[N_NODES];
__device__ int   g_rowstart[N_NODES + 1];
__device__ int   g_cursor[N_NODES];
__device__ int   g_bsum[1024];
__device__ int   g_boff[1024];
__device__ alignas(16) float g_dinv[N_NODES];
__device__ alignas(16) __half g_tmp[(size_t)N_NODES * 64];   // fp16 pre-agg matmul output
__device__ alignas(16) float g_buf0[(size_t)N_NODES * 8];    // aggx (8-wide)
__device__ alignas(16) float g_buf1[(size_t)N_NODES * 64];
__device__ alignas(16) float g_buf2[(size_t)N_NODES * 64];
__device__ alignas(16) float g_gmax[N_GRAPHS * 32];
__device__ alignas(16) float g_gsum[N_GRAPHS * 32];
__device__ int   g_cnt[N_GRAPHS];

__device__ __forceinline__ float* dbuf(int s) {
    switch (s) {
        case 0:  return g_buf0;
        case 1:  return g_buf1;
        default: return g_buf2;
    }
}

__device__ __forceinline__ void red_add_v2(float* addr, float a, float b) {
    asm volatile("red.global.add.v2.f32 [%0], {%1, %2};"
                 :: "l"(addr), "f"(a), "f"(b) : "memory");
}

// ---------------- preprocessing ----------------

// dtype probe: int64 indices (<200000) have all-zero high words.
__global__ void k_detect(const int* __restrict__ ei32) {
    if (threadIdx.x == 0 && blockIdx.x == 0) {
        int is64 = 1;
        #pragma unroll 1
        for (int i = 1; i < 128; i += 2)
            if (ei32[i] != 0) { is64 = 0; break; }
        g_is64 = is64;
    }
}

__global__ void k_init() {
    int i = blockIdx.x * blockDim.x + threadIdx.x;
    if (i < N_NODES) g_deg[i] = 0;
    if (i < N_GRAPHS * 32) { g_gmax[i] = 0.0f; g_gsum[i] = 0.0f; }
    if (i < N_GRAPHS) g_cnt[i] = 0;
    if (i == 0) g_rowstart[N_NODES] = N_EDGES;
}

// degrees only (reads just the dst half of edge_index)
__global__ void k_edges(const void* __restrict__ ei) {
    int e = blockIdx.x * blockDim.x + threadIdx.x;
    if (e >= N_EDGES) return;
    int d;
    if (g_is64) d = (int)((const long long*)ei)[(size_t)N_EDGES + e];
    else        d = ((const int*)ei)[N_EDGES + e];
    atomicAdd(&g_deg[d], 1);
}

__global__ void k_dinv() {
    int i = blockIdx.x * blockDim.x + threadIdx.x;
    if (i >= N_NODES) return;
    g_dinv[i] = rsqrtf((float)g_deg[i] + 1.0f);  // +1 self-loop; always > 0
}

// --- exclusive prefix sum of g_deg -> g_rowstart (3 kernels) ---
__global__ void k_scanA() {
    __shared__ int s[256];
    int i = blockIdx.x * 256 + threadIdx.x;
    s[threadIdx.x] = (i < N_NODES) ? g_deg[i] : 0;
    __syncthreads();
    for (int off = 128; off > 0; off >>= 1) {
        if (threadIdx.x < off) s[threadIdx.x] += s[threadIdx.x + off];
        __syncthreads();
    }
    if (threadIdx.x == 0) g_bsum[blockIdx.x] = s[0];
}

__global__ void k_scanB() {
    __shared__ int s[1024];
    int t = threadIdx.x;
    int own = (t < NB) ? g_bsum[t] : 0;
    s[t] = own;
    __syncthreads();
    for (int off = 1; off < 1024; off <<= 1) {
        int x = (t >= off) ? s[t - off] : 0;
        __syncthreads();
        s[t] += x;
        __syncthreads();
    }
    if (t < NB) g_boff[t] = s[t] - own;  // exclusive
}

__global__ void k_scanC() {
    __shared__ int s[256];
    int i = blockIdx.x * 256 + threadIdx.x;
    int v = (i < N_NODES) ? g_deg[i] : 0;
    s[threadIdx.x] = v;
    __syncthreads();
    for (int off = 1; off < 256; off <<= 1) {
        int x = (threadIdx.x >= off) ? s[threadIdx.x - off] : 0;
        __syncthreads();
        s[threadIdx.x] += x;
        __syncthreads();
    }
    if (i < N_NODES) {
        int start = g_boff[blockIdx.x] + s[threadIdx.x] - v;  // exclusive
        g_rowstart[i] = start;
        g_cursor[i] = start;
    }
}

__global__ void k_fill(const void* __restrict__ ei) {
    int e = blockIdx.x * blockDim.x + threadIdx.x;
    if (e >= N_EDGES) return;
    int s, d;
    if (g_is64) {
        const long long* p = (const long long*)ei;
        s = (int)p[e];
        d = (int)p[(size_t)N_EDGES + e];
    } else {
        const int* p = (const int*)ei;
        s = p[e];
        d = p[N_EDGES + e];
    }
    float nrm = g_dinv[s] * g_dinv[d];
    int pos = atomicAdd(&g_cursor[d], 1);
    g_packed[pos] = make_int2(s, __float_as_int(nrm));
}

// ---------------- dense layers ----------------

// out = act(hin[N,FIN] @ W[FIN,FOUT] + b)
// ACT: -1 none, 0 tanh, 1 relu.  OUT_HALF: write g_tmp (fp16) else dbuf(outSel) fp32.
template <int FIN, int FOUT, int ACT, int OUT_HALF>
__global__ void k_matmul(int hinSel, int outSel,
                         const float* __restrict__ W, const float* __restrict__ b) {
    constexpr int NPB = 256 / FOUT;  // nodes per block
    __shared__ float Ws[FIN * FOUT];
    __shared__ float Xs[NPB * FIN];

    const float* hin = dbuf(hinSel);

    int tid = threadIdx.x;
    for (int k = tid; k < FIN * FOUT; k += 256) Ws[k] = W[k];

    int base = blockIdx.x * NPB;
    for (int k = tid; k < NPB * FIN; k += 256) {
        int node = base + k / FIN;
        Xs[k] = (node < N_NODES) ? hin[(size_t)node * FIN + (k % FIN)] : 0.0f;
    }
    __syncthreads();

    int ln = tid / FOUT;
    int o  = tid % FOUT;
    int node = base + ln;
    if (node >= N_NODES) return;

    float acc = (ACT >= 0) ? b[o] : 0.0f;
    #pragma unroll
    for (int i = 0; i < FIN; i++)
        acc = fmaf(Xs[ln * FIN + i], Ws[i * FOUT + o], acc);
    if (ACT == 0) acc = tanhf(acc);
    if (ACT == 1) acc = fmaxf(acc, 0.0f);

    if (OUT_HALF) g_tmp[(size_t)node * FOUT + o] = __float2half_rn(acc);
    else          dbuf(outSel)[(size_t)node * FOUT + o] = acc;
}

// ---------------- fused aggregates (CSR gather, no atomics) ----------------

// 8-wide aggregate of the RAW INPUT x (fp32): 8 lanes per node.
__global__ void k_agg8(const float* __restrict__ x, int outSel) {
    int gt = blockIdx.x * blockDim.x + threadIdx.x;
    int i = gt >> 3;
    int f = gt & 7;
    if (i >= N_NODES) return;
    float* out = dbuf(outSel);

    float di = g_dinv[i];
    float a0 = x[(size_t)i * 8 + f] * di * di;
    float a1 = 0.0f, a2 = 0.0f, a3 = 0.0f;

    int k = g_rowstart[i];
    int s1 = g_rowstart[i + 1];
    for (; k + 4 <= s1; k += 4) {
        int2 p0 = g_packed[k + 0];
        int2 p1 = g_packed[k + 1];
        int2 p2 = g_packed[k + 2];
        int2 p3 = g_packed[k + 3];
        a0 = fmaf(x[(size_t)p0.x * 8 + f], __int_as_float(p0.y), a0);
        a1 = fmaf(x[(size_t)p1.x * 8 + f], __int_as_float(p1.y), a1);
        a2 = fmaf(x[(size_t)p2.x * 8 + f], __int_as_float(p2.y), a2);
        a3 = fmaf(x[(size_t)p3.x * 8 + f], __int_as_float(p3.y), a3);
    }
    for (; k < s1; k++) {
        int2 p = g_packed[k];
        a0 = fmaf(x[(size_t)p.x * 8 + f], __int_as_float(p.y), a0);
    }
    out[(size_t)i * 8 + f] = a0 + a1 + a2 + a3;
}

// 64-wide: one warp per node, fp16 gather rows (128B/row), fp32 accumulate.
__global__ void k_agg64(int outSel, const float* __restrict__ b) {
    const __half2* __restrict__ tmp = (const __half2*)g_tmp;
    int gw = (blockIdx.x * blockDim.x + threadIdx.x) >> 5;
    int lane = threadIdx.x & 31;
    if (gw >= N_NODES) return;
    const int i = gw;

    float di = g_dinv[i];
    float selfw = di * di;
    float2 vs = __half22float2(tmp[(size_t)i * 32 + lane]);
    float a0x = vs.x * selfw, a0y = vs.y * selfw;
    float a1x = 0.f, a1y = 0.f, a2x = 0.f, a2y = 0.f, a3x = 0.f, a3y = 0.f;

    int k = g_rowstart[i];
    int s1 = g_rowstart[i + 1];
    for (; k + 4 <= s1; k += 4) {
        int2 p0 = g_packed[k + 0];
        int2 p1 = g_packed[k + 1];
        int2 p2 = g_packed[k + 2];
        int2 p3 = g_packed[k + 3];
        float2 v0 = __half22float2(tmp[(size_t)p0.x * 32 + lane]);
        float2 v1 = __half22float2(tmp[(size_t)p1.x * 32 + lane]);
        float2 v2 = __half22float2(tmp[(size_t)p2.x * 32 + lane]);
        float2 v3 = __half22float2(tmp[(size_t)p3.x * 32 + lane]);
        float n0 = __int_as_float(p0.y), n1 = __int_as_float(p1.y);
        float n2 = __int_as_float(p2.y), n3 = __int_as_float(p3.y);
        a0x = fmaf(v0.x, n0, a0x); a0y = fmaf(v0.y, n0, a0y);
        a1x = fmaf(v1.x, n1, a1x); a1y = fmaf(v1.y, n1, a1y);
        a2x = fmaf(v2.x, n2, a2x); a2y = fmaf(v2.y, n2, a2y);
        a3x = fmaf(v3.x, n3, a3x); a3y = fmaf(v3.y, n3, a3y);
    }
    for (; k < s1; k++) {
        int2 p = g_packed[k];
        float nrm = __int_as_float(p.y);
        float2 v = __half22float2(tmp[(size_t)p.x * 32 + lane]);
        a0x = fmaf(v.x, nrm, a0x); a0y = fmaf(v.y, nrm, a0y);
    }

    float acc0 = (a0x + a1x) + (a2x + a3x);
    float acc1 = (a0y + a1y) + (a2y + a3y);
    acc0 = fmaxf(acc0 + b[lane * 2], 0.0f);       // relu (layer 1 only)
    acc1 = fmaxf(acc1 + b[lane * 2 + 1], 0.0f);

    float* out = dbuf(outSel);
    *(float2*)(out + (size_t)i * 64 + lane * 2) = make_float2(acc0, acc1);
}

// 32-wide: 2 nodes per warp (16 lanes each, half2 per lane), fp32 accumulate.
// POOL=1: fused pooling (relu output >= 0), no dense write.
template <int POOL>
__global__ void k_agg32(int outSel, const float* __restrict__ b,
                        const void* __restrict__ batch) {
    const __half2* __restrict__ tmp = (const __half2*)g_tmp;
    int gw = (blockIdx.x * blockDim.x + threadIdx.x) >> 5;
    int lane = threadIdx.x & 31;
    int sub  = lane >> 4;         // which node in this warp
    int fl   = lane & 15;         // half2 index within row (feature = 2*fl)
    int i = gw * 2 + sub;
    if (i >= N_NODES) return;

    float di = g_dinv[i];
    float selfw = di * di;
    float2 vs = __half22float2(tmp[(size_t)i * 16 + fl]);
    float a0x = vs.x * selfw, a0y = vs.y * selfw;
    float a1x = 0.f, a1y = 0.f, a2x = 0.f, a2y = 0.f, a3x = 0.f, a3y = 0.f;

    int k = g_rowstart[i];
    int s1 = g_rowstart[i + 1];
    for (; k + 4 <= s1; k += 4) {
        int2 p0 = g_packed[k + 0];
        int2 p1 = g_packed[k + 1];
        int2 p2 = g_packed[k + 2];
        int2 p3 = g_packed[k + 3];
        float2 v0 = __half22float2(tmp[(size_t)p0.x * 16 + fl]);
        float2 v1 = __half22float2(tmp[(size_t)p1.x * 16 + fl]);
        float2 v2 = __half22float2(tmp[(size_t)p2.x * 16 + fl]);
        float2 v3 = __half22float2(tmp[(size_t)p3.x * 16 + fl]);
        float n0 = __int_as_float(p0.y), n1 = __int_as_float(p1.y);
        float n2 = __int_as_float(p2.y), n3 = __int_as_float(p3.y);
        a0x = fmaf(v0.x, n0, a0x); a0y = fmaf(v0.y, n0, a0y);
        a1x = fmaf(v1.x, n1, a1x); a1y = fmaf(v1.y, n1, a1y);
        a2x = fmaf(v2.x, n2, a2x); a2y = fmaf(v2.y, n2, a2y);
        a3x = fmaf(v3.x, n3, a3x); a3y = fmaf(v3.y, n3, a3y);
    }
    for (; k < s1; k++) {
        int2 p = g_packed[k];
        float nrm = __int_as_float(p.y);
        float2 v = __half22float2(tmp[(size_t)p.x * 16 + fl]);
        a0x = fmaf(v.x, nrm, a0x); a0y = fmaf(v.y, nrm, a0y);
    }

    float acc0 = (a0x + a1x) + (a2x + a3x);
    float acc1 = (a0y + a1y) + (a2y + a3y);
    acc0 = fmaxf(acc0 + b[fl * 2], 0.0f);         // relu
    acc1 = fmaxf(acc1 + b[fl * 2 + 1], 0.0f);

    if (POOL) {
        int g;
        if (g_is64) g = (int)((const long long*)batch)[i];
        else        g = ((const int*)batch)[i];
        red_add_v2(&g_gsum[g * 32 + fl * 2], acc0, acc1);
        int* mx = (int*)&g_gmax[g * 32 + fl * 2];
        atomicMax(mx + 0, __float_as_int(acc0));  // acc >= 0
        atomicMax(mx + 1, __float_as_int(acc1));
        if (fl == 0) atomicAdd(&g_cnt[g], 1);
    } else {
        float* out = dbuf(outSel);
        *(float2*)(out + (size_t)i * 32 + fl * 2) = make_float2(acc0, acc1);
    }
}

// out[g, o] = concat(gmax, gmean) @ Wout + bout
__global__ void k_out(const float* __restrict__ Wout, const float* __restrict__ bout,
                      float* __restrict__ out) {
    int idx = blockIdx.x * blockDim.x + threadIdx.x;
    if (idx >= N_GRAPHS * 10) return;
    int g = idx / 10;
    int o = idx % 10;
    float cnt = (float)g_cnt[g];
    float inv = 1.0f / fmaxf(cnt, 1.0f);
    float acc = bout[o];
    #pragma unroll 8
    for (int f = 0; f < 32; f++) {
        acc = fmaf(g_gmax[g * 32 + f], Wout[f * 10 + o], acc);
        acc = fmaf(g_gsum[g * 32 + f] * inv, Wout[(32 + f) * 10 + o], acc);
    }
    out[idx] = acc;
}

// x -> buf0 copy path for layer-0 matmul input (aggx)
__global__ void k_dummy() {}

// ---------------- launch ----------------

static inline int cdiv(long long a, int b) { return (int)((a + b - 1) / b); }

// matmul for fp32 external x input (layer 0 after agg8 uses dbuf, so not needed)

extern "C" void kernel_launch(void* const* d_in, const int* in_sizes, int n_in,
                              void* d_out, int out_size) {
    const float* x     = (const float*)d_in[0];
    const void*  ei    = d_in[1];
    const void*  batch = d_in[2];
    const float* W0   = (const float*)d_in[3];
    const float* b0   = (const float*)d_in[4];
    const float* W1   = (const float*)d_in[5];
    const float* b1   = (const float*)d_in[6];
    const float* W2   = (const float*)d_in[7];
    const float* b2   = (const float*)d_in[8];
    const float* W3   = (const float*)d_in[9];
    const float* b3   = (const float*)d_in[10];
    const float* Wout = (const float*)d_in[11];
    const float* bout = (const float*)d_in[12];
    float* out = (float*)d_out;

    const int T = 256;
    const int AGG64_BLOCKS = cdiv((long long)N_NODES * 32, T);
    const int AGG32_BLOCKS = cdiv((long long)N_NODES * 16, T);

    // preprocessing: probe, degrees, dinv, CSR
    k_detect<<<1, 32>>>((const int*)ei);
    k_init<<<cdiv(N_NODES, T), T>>>();
    k_edges<<<cdiv(N_EDGES, T), T>>>(ei);
    k_dinv<<<cdiv(N_NODES, T), T>>>();
    k_scanA<<<NB, 256>>>();
    k_scanB<<<1, 1024>>>();
    k_scanC<<<NB, 256>>>();
    k_fill<<<cdiv(N_EDGES, T), T>>>(ei);

    // Layer 0 (linearity): aggx = agg(x) [8-wide, fp32] -> buf0;
    // h1 = tanh(aggx @ W0 + b0) -> buf1 (fp32)
    k_agg8<<<cdiv((long long)N_NODES * 8, T), T>>>(x, 0);
    k_matmul<8, 64, 0, 0><<<cdiv(N_NODES, 256 / 64), T>>>(0, 1, W0, b0);

    // Layer 1: tmp16 = h1 @ W1; h2 = relu(agg(tmp16) + b1) -> buf2
    k_matmul<64, 64, -1, 1><<<cdiv(N_NODES, 256 / 64), T>>>(1, 0, W1, nullptr);
    k_agg64<<<AGG64_BLOCKS, T>>>(2, b1);

    // Layer 2: tmp16 = h2 @ W2; h3 = relu(agg(tmp16) + b2) -> buf1
    k_matmul<64, 32, -1, 1><<<cdiv(N_NODES, 256 / 32), T>>>(2, 0, W2, nullptr);
    k_agg32<0><<<AGG32_BLOCKS, T>>>(1, b2, nullptr);

    // Layer 3: tmp16 = h3 @ W3; agg+bias+relu fused with pooling
    k_matmul<32, 32, -1, 1><<<cdiv(N_NODES, 256 / 32), T>>>(1, 0, W3, nullptr);
    k_agg32<1><<<AGG32_BLOCKS, T>>>(0, b3, batch);

    k_out<<<cdiv(N_GRAPHS * 10, T), T>>>(Wout, bout, out);
}

// round 10
// speedup vs baseline: 2.1905x; 1.3048x over previous
#include <cuda_runtime.h>
#include <cuda_fp16.h>
#include <math.h>

#define N_NODES 200000
#define N_EDGES 3200000
#define N_GRAPHS 1024
#define NB 782   // cdiv(N_NODES, 256)

// ---------------- scratch (static device globals; no allocation) ----------------
__device__ int   g_is64;
__device__ alignas(16) int2 g_packed[N_EDGES];   // CSR payload: {src, bitcast(norm)}
__device__ int   g_deg[N_NODES];
__device__ int   g_rowstart[N_NODES + 1];
__device__ int   g_cursor[N_NODES];
__device__ int   g_bsum[1024];
__device__ int   g_boff[1024];
__device__ alignas(16) float g_dinv[N_NODES];
__device__ alignas(16) __half g_tmp[(size_t)N_NODES * 64];   // fp16 pre-agg matmul output
__device__ alignas(16) float g_buf0[(size_t)N_NODES * 8];    // aggx (8-wide)
__device__ alignas(16) float g_buf1[(size_t)N_NODES * 64];
__device__ alignas(16) float g_buf2[(size_t)N_NODES * 64];
__device__ alignas(16) float g_gmax[N_GRAPHS * 32];
__device__ alignas(16) float g_gsum[N_GRAPHS * 32];
__device__ int   g_cnt[N_GRAPHS];

__device__ __forceinline__ float* dbuf(int s) {
    switch (s) {
        case 0:  return g_buf0;
        case 1:  return g_buf1;
        default: return g_buf2;
    }
}

__device__ __forceinline__ void red_add_v2(float* addr, float a, float b) {
    asm volatile("red.global.add.v2.f32 [%0], {%1, %2};"
                 :: "l"(addr), "f"(a), "f"(b) : "memory");
}

// ---------------- preprocessing ----------------

// dtype probe: int64 indices (<200000) have all-zero high words.
__global__ void k_detect(const int* __restrict__ ei32) {
    if (threadIdx.x == 0 && blockIdx.x == 0) {
        int is64 = 1;
        #pragma unroll 1
        for (int i = 1; i < 128; i += 2)
            if (ei32[i] != 0) { is64 = 0; break; }
        g_is64 = is64;
    }
}

__global__ void k_init() {
    int i = blockIdx.x * blockDim.x + threadIdx.x;
    if (i < N_NODES) g_deg[i] = 0;
    if (i < N_GRAPHS * 32) { g_gmax[i] = 0.0f; g_gsum[i] = 0.0f; }
    if (i < N_GRAPHS) g_cnt[i] = 0;
    if (i == 0) g_rowstart[N_NODES] = N_EDGES;
}

// degrees only (reads just the dst half of edge_index)
__global__ void k_edges(const void* __restrict__ ei) {
    int e = blockIdx.x * blockDim.x + threadIdx.x;
    if (e >= N_EDGES) return;
    int d;
    if (g_is64) d = (int)((const long long*)ei)[(size_t)N_EDGES + e];
    else        d = ((const int*)ei)[N_EDGES + e];
    atomicAdd(&g_deg[d], 1);
}

__global__ void k_dinv() {
    int i = blockIdx.x * blockDim.x + threadIdx.x;
    if (i >= N_NODES) return;
    g_dinv[i] = rsqrtf((float)g_deg[i] + 1.0f);  // +1 self-loop; always > 0
}

// --- exclusive prefix sum of g_deg -> g_rowstart (3 kernels) ---
__global__ void k_scanA() {
    __shared__ int s[256];
    int i = blockIdx.x * 256 + threadIdx.x;
    s[threadIdx.x] = (i < N_NODES) ? g_deg[i] : 0;
    __syncthreads();
    for (int off = 128; off > 0; off >>= 1) {
        if (threadIdx.x < off) s[threadIdx.x] += s[threadIdx.x + off];
        __syncthreads();
    }
    if (threadIdx.x == 0) g_bsum[blockIdx.x] = s[0];
}

__global__ void k_scanB() {
    __shared__ int s[1024];
    int t = threadIdx.x;
    int own = (t < NB) ? g_bsum[t] : 0;
    s[t] = own;
    __syncthreads();
    for (int off = 1; off < 1024; off <<= 1) {
        int x = (t >= off) ? s[t - off] : 0;
        __syncthreads();
        s[t] += x;
        __syncthreads();
    }
    if (t < NB) g_boff[t] = s[t] - own;  // exclusive
}

__global__ void k_scanC() {
    __shared__ int s[256];
    int i = blockIdx.x * 256 + threadIdx.x;
    int v = (i < N_NODES) ? g_deg[i] : 0;
    s[threadIdx.x] = v;
    __syncthreads();
    for (int off = 1; off < 256; off <<= 1) {
        int x = (threadIdx.x >= off) ? s[threadIdx.x - off] : 0;
        __syncthreads();
        s[threadIdx.x] += x;
        __syncthreads();
    }
    if (i < N_NODES) {
        int start = g_boff[blockIdx.x] + s[threadIdx.x] - v;  // exclusive
        g_rowstart[i] = start;
        g_cursor[i] = start;
    }
}

__global__ void k_fill(const void* __restrict__ ei) {
    int e = blockIdx.x * blockDim.x + threadIdx.x;
    if (e >= N_EDGES) return;
    int s, d;
    if (g_is64) {
        const long long* p = (const long long*)ei;
        s = (int)p[e];
        d = (int)p[(size_t)N_EDGES + e];
    } else {
        const int* p = (const int*)ei;
        s = p[e];
        d = p[N_EDGES + e];
    }
    float nrm = g_dinv[s] * g_dinv[d];
    int pos = atomicAdd(&g_cursor[d], 1);
    g_packed[pos] = make_int2(s, __float_as_int(nrm));
}

// ---------------- dense layers: register-tiled block GEMM ----------------
// blockDim 256, NPB nodes per block (NPB*FOUT == 4096), 4x4 tile per thread.
// out = act(hin[N,FIN] @ W[FIN,FOUT] + b); ACT: -1 none, 0 tanh, 1 relu.
// OUT_HALF: write g_tmp (fp16) else dbuf(outSel) (fp32).
template <int FIN, int FOUT, int ACT, int OUT_HALF, int NPB>
__global__ void k_matmul(int hinSel, int outSel,
                         const float* __restrict__ W, const float* __restrict__ b) {
    static_assert(NPB * FOUT == 4096, "tile math");
    __shared__ float Ws[FIN * FOUT];
    __shared__ float Xs[FIN * NPB];   // transposed: Xs[i][node]

    const float* hin = dbuf(hinSel);
    int tid = threadIdx.x;
    int base = blockIdx.x * NPB;

    for (int k = tid; k < FIN * FOUT / 4; k += 256)
        ((float4*)Ws)[k] = ((const float4*)W)[k];

    for (int k = tid; k < NPB * FIN; k += 256) {
        int n = k / FIN, i = k % FIN;
        int node = base + n;
        Xs[i * NPB + n] = (node < N_NODES) ? hin[(size_t)node * FIN + i] : 0.0f;
    }
    __syncthreads();

    constexpr int OT = FOUT / 4;       // 4-output tiles per row
    int ob = (tid % OT) * 4;
    int nb = (tid / OT) * 4;

    float acc[4][4];
    #pragma unroll
    for (int n = 0; n < 4; n++) {
        #pragma unroll
        for (int o = 0; o < 4; o++)
            acc[n][o] = (ACT >= 0) ? b[ob + o] : 0.0f;
    }

    #pragma unroll
    for (int i = 0; i < FIN; i++) {
        float4 w  = *(const float4*)&Ws[i * FOUT + ob];
        float4 xv = *(const float4*)&Xs[i * NPB + nb];
        acc[0][0] = fmaf(xv.x, w.x, acc[0][0]); acc[0][1] = fmaf(xv.x, w.y, acc[0][1]);
        acc[0][2] = fmaf(xv.x, w.z, acc[0][2]); acc[0][3] = fmaf(xv.x, w.w, acc[0][3]);
        acc[1][0] = fmaf(xv.y, w.x, acc[1][0]); acc[1][1] = fmaf(xv.y, w.y, acc[1][1]);
        acc[1][2] = fmaf(xv.y, w.z, acc[1][2]); acc[1][3] = fmaf(xv.y, w.w, acc[1][3]);
        acc[2][0] = fmaf(xv.z, w.x, acc[2][0]); acc[2][1] = fmaf(xv.z, w.y, acc[2][1]);
        acc[2][2] = fmaf(xv.z, w.z, acc[2][2]); acc[2][3] = fmaf(xv.z, w.w, acc[2][3]);
        acc[3][0] = fmaf(xv.w, w.x, acc[3][0]); acc[3][1] = fmaf(xv.w, w.y, acc[3][1]);
        acc[3][2] = fmaf(xv.w, w.z, acc[3][2]); acc[3][3] = fmaf(xv.w, w.w, acc[3][3]);
    }

    #pragma unroll
    for (int n = 0; n < 4; n++) {
        int node = base + nb + n;
        if (node >= N_NODES) continue;
        #pragma unroll
        for (int o = 0; o < 4; o++) {
            float v = acc[n][o];
            if (ACT == 0) v = tanhf(v);
            if (ACT == 1) v = fmaxf(v, 0.0f);
            acc[n][o] = v;
        }
        if (OUT_HALF) {
            __half2* dst = (__half2*)&g_tmp[(size_t)node * FOUT + ob];
            dst[0] = __floats2half2_rn(acc[n][0], acc[n][1]);
            dst[1] = __floats2half2_rn(acc[n][2], acc[n][3]);
        } else {
            *(float4*)&dbuf(outSel)[(size_t)node * FOUT + ob] =
                make_float4(acc[n][0], acc[n][1], acc[n][2], acc[n][3]);
        }
    }
}

// ---------------- fused aggregates (CSR gather, no atomics) ----------------

// 8-wide aggregate of the RAW INPUT x (fp32): 8 lanes per node.
__global__ void k_agg8(const float* __restrict__ x, int outSel) {
    int gt = blockIdx.x * blockDim.x + threadIdx.x;
    int i = gt >> 3;
    int f = gt & 7;
    if (i >= N_NODES) return;
    float* out = dbuf(outSel);

    float di = g_dinv[i];
    float a0 = x[(size_t)i * 8 + f] * di * di;
    float a1 = 0.0f, a2 = 0.0f, a3 = 0.0f;

    int k = g_rowstart[i];
    int s1 = g_rowstart[i + 1];
    for (; k + 4 <= s1; k += 4) {
        int2 p0 = g_packed[k + 0];
        int2 p1 = g_packed[k + 1];
        int2 p2 = g_packed[k + 2];
        int2 p3 = g_packed[k + 3];
        a0 = fmaf(x[(size_t)p0.x * 8 + f], __int_as_float(p0.y), a0);
        a1 = fmaf(x[(size_t)p1.x * 8 + f], __int_as_float(p1.y), a1);
        a2 = fmaf(x[(size_t)p2.x * 8 + f], __int_as_float(p2.y), a2);
        a3 = fmaf(x[(size_t)p3.x * 8 + f], __int_as_float(p3.y), a3);
    }
    for (; k < s1; k++) {
        int2 p = g_packed[k];
        a0 = fmaf(x[(size_t)p.x * 8 + f], __int_as_float(p.y), a0);
    }
    out[(size_t)i * 8 + f] = a0 + a1 + a2 + a3;
}

// 64-wide: one warp per node, fp16 gather rows (128B/row), fp32 accumulate.
__global__ void k_agg64(int outSel, const float* __restrict__ b) {
    const __half2* __restrict__ tmp = (const __half2*)g_tmp;
    int gw = (blockIdx.x * blockDim.x + threadIdx.x) >> 5;
    int lane = threadIdx.x & 31;
    if (gw >= N_NODES) return;
    const int i = gw;

    float di = g_dinv[i];
    float selfw = di * di;
    float2 vs = __half22float2(tmp[(size_t)i * 32 + lane]);
    float a0x = vs.x * selfw, a0y = vs.y * selfw;
    float a1x = 0.f, a1y = 0.f, a2x = 0.f, a2y = 0.f, a3x = 0.f, a3y = 0.f;

    int k = g_rowstart[i];
    int s1 = g_rowstart[i + 1];
    for (; k + 4 <= s1; k += 4) {
        int2 p0 = g_packed[k + 0];
        int2 p1 = g_packed[k + 1];
        int2 p2 = g_packed[k + 2];
        int2 p3 = g_packed[k + 3];
        float2 v0 = __half22float2(tmp[(size_t)p0.x * 32 + lane]);
        float2 v1 = __half22float2(tmp[(size_t)p1.x * 32 + lane]);
        float2 v2 = __half22float2(tmp[(size_t)p2.x * 32 + lane]);
        float2 v3 = __half22float2(tmp[(size_t)p3.x * 32 + lane]);
        float n0 = __int_as_float(p0.y), n1 = __int_as_float(p1.y);
        float n2 = __int_as_float(p2.y), n3 = __int_as_float(p3.y);
        a0x = fmaf(v0.x, n0, a0x); a0y = fmaf(v0.y, n0, a0y);
        a1x = fmaf(v1.x, n1, a1x); a1y = fmaf(v1.y, n1, a1y);
        a2x = fmaf(v2.x, n2, a2x); a2y = fmaf(v2.y, n2, a2y);
        a3x = fmaf(v3.x, n3, a3x); a3y = fmaf(v3.y, n3, a3y);
    }
    for (; k < s1; k++) {
        int2 p = g_packed[k];
        float nrm = __int_as_float(p.y);
        float2 v = __half22float2(tmp[(size_t)p.x * 32 + lane]);
        a0x = fmaf(v.x, nrm, a0x); a0y = fmaf(v.y, nrm, a0y);
    }

    float acc0 = (a0x + a1x) + (a2x + a3x);
    float acc1 = (a0y + a1y) + (a2y + a3y);
    acc0 = fmaxf(acc0 + b[lane * 2], 0.0f);       // relu (layer 1 only)
    acc1 = fmaxf(acc1 + b[lane * 2 + 1], 0.0f);

    float* out = dbuf(outSel);
    *(float2*)(out + (size_t)i * 64 + lane * 2) = make_float2(acc0, acc1);
}

// 32-wide: 2 nodes per warp (16 lanes each, half2 per lane), fp32 accumulate.
// POOL=1: fused pooling (relu output >= 0), no dense write.
template <int POOL>
__global__ void k_agg32(int outSel, const float* __restrict__ b,
                        const void* __restrict__ batch) {
    const __half2* __restrict__ tmp = (const __half2*)g_tmp;
    int gw = (blockIdx.x * blockDim.x + threadIdx.x) >> 5;
    int lane = threadIdx.x & 31;
    int sub  = lane >> 4;         // which node in this warp
    int fl   = lane & 15;         // half2 index within row (feature = 2*fl)
    int i = gw * 2 + sub;
    if (i >= N_NODES) return;

    float di = g_dinv[i];
    float selfw = di * di;
    float2 vs = __half22float2(tmp[(size_t)i * 16 + fl]);
    float a0x = vs.x * selfw, a0y = vs.y * selfw;
    float a1x = 0.f, a1y = 0.f, a2x = 0.f, a2y = 0.f, a3x = 0.f, a3y = 0.f;

    int k = g_rowstart[i];
    int s1 = g_rowstart[i + 1];
    for (; k + 4 <= s1; k += 4) {
        int2 p0 = g_packed[k + 0];
        int2 p1 = g_packed[k + 1];
        int2 p2 = g_packed[k + 2];
        int2 p3 = g_packed[k + 3];
        float2 v0 = __half22float2(tmp[(size_t)p0.x * 16 + fl]);
        float2 v1 = __half22float2(tmp[(size_t)p1.x * 16 + fl]);
        float2 v2 = __half22float2(tmp[(size_t)p2.x * 16 + fl]);
        float2 v3 = __half22float2(tmp[(size_t)p3.x * 16 + fl]);
        float n0 = __int_as_float(p0.y), n1 = __int_as_float(p1.y);
        float n2 = __int_as_float(p2.y), n3 = __int_as_float(p3.y);
        a0x = fmaf(v0.x, n0, a0x); a0y = fmaf(v0.y, n0, a0y);
        a1x = fmaf(v1.x, n1, a1x); a1y = fmaf(v1.y, n1, a1y);
        a2x = fmaf(v2.x, n2, a2x); a2y = fmaf(v2.y, n2, a2y);
        a3x = fmaf(v3.x, n3, a3x); a3y = fmaf(v3.y, n3, a3y);
    }
    for (; k < s1; k++) {
        int2 p = g_packed[k];
        float nrm = __int_as_float(p.y);
        float2 v = __half22float2(tmp[(size_t)p.x * 16 + fl]);
        a0x = fmaf(v.x, nrm, a0x); a0y = fmaf(v.y, nrm, a0y);
    }

    float acc0 = (a0x + a1x) + (a2x + a3x);
    float acc1 = (a0y + a1y) + (a2y + a3y);
    acc0 = fmaxf(acc0 + b[fl * 2], 0.0f);         // relu
    acc1 = fmaxf(acc1 + b[fl * 2 + 1], 0.0f);

    if (POOL) {
        int g;
        if (g_is64) g = (int)((const long long*)batch)[i];
        else        g = ((const int*)batch)[i];
        red_add_v2(&g_gsum[g * 32 + fl * 2], acc0, acc1);
        int* mx = (int*)&g_gmax[g * 32 + fl * 2];
        atomicMax(mx + 0, __float_as_int(acc0));  // acc >= 0
        atomicMax(mx + 1, __float_as_int(acc1));
        if (fl == 0) atomicAdd(&g_cnt[g], 1);
    } else {
        float* out = dbuf(outSel);
        *(float2*)(out + (size_t)i * 32 + fl * 2) = make_float2(acc0, acc1);
    }
}

// out[g, o] = concat(gmax, gmean) @ Wout + bout
__global__ void k_out(const float* __restrict__ Wout, const float* __restrict__ bout,
                      float* __restrict__ out) {
    int idx = blockIdx.x * blockDim.x + threadIdx.x;
    if (idx >= N_GRAPHS * 10) return;
    int g = idx / 10;
    int o = idx % 10;
    float cnt = (float)g_cnt[g];
    float inv = 1.0f / fmaxf(cnt, 1.0f);
    float acc = bout[o];
    #pragma unroll 8
    for (int f = 0; f < 32; f++) {
        acc = fmaf(g_gmax[g * 32 + f], Wout[f * 10 + o], acc);
        acc = fmaf(g_gsum[g * 32 + f] * inv, Wout[(32 + f) * 10 + o], acc);
    }
    out[idx] = acc;
}

// ---------------- launch ----------------

static inline int cdiv(long long a, int b) { return (int)((a + b - 1) / b); }

extern "C" void kernel_launch(void* const* d_in, const int* in_sizes, int n_in,
                              void* d_out, int out_size) {
    const float* x     = (const float*)d_in[0];
    const void*  ei    = d_in[1];
    const void*  batch = d_in[2];
    const float* W0   = (const float*)d_in[3];
    const float* b0   = (const float*)d_in[4];
    const float* W1   = (const float*)d_in[5];
    const float* b1   = (const float*)d_in[6];
    const float* W2   = (const float*)d_in[7];
    const float* b2   = (const float*)d_in[8];
    const float* W3   = (const float*)d_in[9];
    const float* b3   = (const float*)d_in[10];
    const float* Wout = (const float*)d_in[11];
    const float* bout = (const float*)d_in[12];
    float* out = (float*)d_out;

    const int T = 256;
    const int AGG64_BLOCKS = cdiv((long long)N_NODES * 32, T);
    const int AGG32_BLOCKS = cdiv((long long)N_NODES * 16, T);

    // preprocessing: probe, degrees, dinv, CSR
    k_detect<<<1, 32>>>((const int*)ei);
    k_init<<<cdiv(N_NODES, T), T>>>();
    k_edges<<<cdiv(N_EDGES, T), T>>>(ei);
    k_dinv<<<cdiv(N_NODES, T), T>>>();
    k_scanA<<<NB, 256>>>();
    k_scanB<<<1, 1024>>>();
    k_scanC<<<NB, 256>>>();
    k_fill<<<cdiv(N_EDGES, T), T>>>(ei);

    // Layer 0 (linearity): aggx = agg(x) [8-wide, fp32] -> buf0;
    // h1 = tanh(aggx @ W0 + b0) -> buf1 (fp32)
    k_agg8<<<cdiv((long long)N_NODES * 8, T), T>>>(x, 0);
    k_matmul<8, 64, 0, 0, 64><<<cdiv(N_NODES, 64), T>>>(0, 1, W0, b0);

    // Layer 1: tmp16 = h1 @ W1; h2 = relu(agg(tmp16) + b1) -> buf2
    k_matmul<64, 64, -1, 1, 64><<<cdiv(N_NODES, 64), T>>>(1, 0, W1, nullptr);
    k_agg64<<<AGG64_BLOCKS, T>>>(2, b1);

    // Layer 2: tmp16 = h2 @ W2; h3 = relu(agg(tmp16) + b2) -> buf1
    k_matmul<64, 32, -1, 1, 128><<<cdiv(N_NODES, 128), T>>>(2, 0, W2, nullptr);
    k_agg32<0><<<AGG32_BLOCKS, T>>>(1, b2, nullptr);

    // Layer 3: tmp16 = h3 @ W3; agg+bias+relu fused with pooling
    k_matmul<32, 32, -1, 1, 128><<<cdiv(N_NODES, 128), T>>>(1, 0, W3, nullptr);
    k_agg32<1><<<AGG32_BLOCKS, T>>>(0, b3, batch);

    k_out<<<cdiv(N_GRAPHS * 10, T), T>>>(Wout, bout, out);
}